// round 5
// baseline (speedup 1.0000x reference)
#include <cuda_runtime.h>
#include <cuda_bf16.h>
#include <cstdint>

// y[t, f] = x[t, f] * w[f] + b[f]
// x: [8192, 4096] f32 (128 MiB), w/b: [4096] f32, out: same shape.
//
// Pure HBM-streaming kernel (cache-residency tricks measured as losses in R4).
// R1 structure (flat map, 1 item/thread, high occupancy) + 256-bit loads:
// ld.global.nc.v8.b32 halves LDG count per byte; stores stay default STG.128.

#define TOKENS      8192
#define IN_FEATURES 4096
#define COLS8       (IN_FEATURES / 8)    // 512 column-octets, pow2
#define N8          (TOKENS * COLS8)     // 4,194,304 octets

struct f8 { float v[8]; };

__device__ __forceinline__ f8 ldg256(const float* p) {
    uint32_t r0, r1, r2, r3, r4, r5, r6, r7;
    asm("ld.global.nc.v8.b32 {%0,%1,%2,%3,%4,%5,%6,%7}, [%8];"
        : "=r"(r0), "=r"(r1), "=r"(r2), "=r"(r3),
          "=r"(r4), "=r"(r5), "=r"(r6), "=r"(r7)
        : "l"(p));
    f8 o;
    o.v[0] = __uint_as_float(r0); o.v[1] = __uint_as_float(r1);
    o.v[2] = __uint_as_float(r2); o.v[3] = __uint_as_float(r3);
    o.v[4] = __uint_as_float(r4); o.v[5] = __uint_as_float(r5);
    o.v[6] = __uint_as_float(r6); o.v[7] = __uint_as_float(r7);
    return o;
}

__global__ __launch_bounds__(256) void one_to_one_kernel(
    const float* __restrict__ x,
    const float* __restrict__ w,
    const float* __restrict__ b,
    float* __restrict__ out)
{
    int i = blockIdx.x * blockDim.x + threadIdx.x;   // octet index, 0..N8-1
    int col = (i & (COLS8 - 1)) * 8;                 // column within the row

    const float* xp = x + (long)i * 8;
    float*       op = out + (long)i * 8;

    // w/b: 16 KiB each, L1/L2-resident
    float4 w0 = __ldg((const float4*)(w + col));
    float4 w1 = __ldg((const float4*)(w + col + 4));
    float4 b0 = __ldg((const float4*)(b + col));
    float4 b1 = __ldg((const float4*)(b + col + 4));

    f8 xv = ldg256(xp);

    float4 r0, r1;
    r0.x = fmaf(xv.v[0], w0.x, b0.x);
    r0.y = fmaf(xv.v[1], w0.y, b0.y);
    r0.z = fmaf(xv.v[2], w0.z, b0.z);
    r0.w = fmaf(xv.v[3], w0.w, b0.w);
    r1.x = fmaf(xv.v[4], w1.x, b1.x);
    r1.y = fmaf(xv.v[5], w1.y, b1.y);
    r1.z = fmaf(xv.v[6], w1.z, b1.z);
    r1.w = fmaf(xv.v[7], w1.w, b1.w);

    ((float4*)op)[0] = r0;
    ((float4*)op)[1] = r1;
}

extern "C" void kernel_launch(void* const* d_in, const int* in_sizes, int n_in,
                              void* d_out, int out_size)
{
    const float* x = (const float*)d_in[0];
    const float* w = (const float*)d_in[1];
    const float* b = (const float*)d_in[2];
    float* out = (float*)d_out;

    const int threads = 256;
    const int blocks  = N8 / threads;   // 16384
    one_to_one_kernel<<<blocks, threads>>>(x, w, b, out);
}

// round 6
// speedup vs baseline: 1.5533x; 1.5533x over previous
#include <cuda_runtime.h>
#include <cuda_bf16.h>

// y[t, f] = x[t, f] * w[f] + b[f]
// x: [8192, 4096] f32 (128 MiB), w/b: [4096] f32, out: same shape.
//
// Pure HBM streaming. Measured facts on sm_103a:
//  - LDG.128 is the right width (v8/256-bit loads tank L1tex: R5 = 66us).
//  - L2-residency games lose (R4).
// This round: R1 structure + ILP=2 split-half mapping. Thread i handles quad i
// and quad i + N4/2 — same column (N4/2 % COLS4 == 0) so w/b load once; two
// independent LDG.128 front-batched for 2x MLP at ~same register count.

#define TOKENS      8192
#define IN_FEATURES 4096
#define COLS4       (IN_FEATURES / 4)    // 1024, pow2
#define N4          (TOKENS * COLS4)     // 8,388,608 quads
#define HALF4       (N4 / 2)             // 4,194,304

__global__ __launch_bounds__(256) void one_to_one_kernel(
    const float4* __restrict__ x,
    const float4* __restrict__ w,
    const float4* __restrict__ b,
    float4* __restrict__ out)
{
    int i = blockIdx.x * blockDim.x + threadIdx.x;   // 0 .. HALF4-1
    int c = i & (COLS4 - 1);                          // column quad (same for both halves)

    // Two independent streaming loads, front-batched
    float4 x0 = x[i];
    float4 x1 = x[i + HALF4];

    float4 wv = __ldg(&w[c]);
    float4 bv = __ldg(&b[c]);

    float4 r0, r1;
    r0.x = fmaf(x0.x, wv.x, bv.x);
    r0.y = fmaf(x0.y, wv.y, bv.y);
    r0.z = fmaf(x0.z, wv.z, bv.z);
    r0.w = fmaf(x0.w, wv.w, bv.w);
    r1.x = fmaf(x1.x, wv.x, bv.x);
    r1.y = fmaf(x1.y, wv.y, bv.y);
    r1.z = fmaf(x1.z, wv.z, bv.z);
    r1.w = fmaf(x1.w, wv.w, bv.w);

    out[i]         = r0;
    out[i + HALF4] = r1;
}

extern "C" void kernel_launch(void* const* d_in, const int* in_sizes, int n_in,
                              void* d_out, int out_size)
{
    const float4* x = (const float4*)d_in[0];
    const float4* w = (const float4*)d_in[1];
    const float4* b = (const float4*)d_in[2];
    float4* out = (float4*)d_out;

    const int threads = 256;
    const int blocks  = HALF4 / threads;   // 16384
    one_to_one_kernel<<<blocks, threads>>>(x, w, b, out);
}